// round 3
// baseline (speedup 1.0000x reference)
#include <cuda_runtime.h>
#include <math.h>

#define SEQ 4096
#define DM  1024
#define NH  16
#define DK  64

// Scratch (allocation-guard-safe __device__ globals): Q,K,V projections + attn out
__device__ float g_Q[SEQ * DM];
__device__ float g_K[SEQ * DM];
__device__ float g_V[SEQ * DM];
__device__ float g_O[SEQ * DM];

// ---------------------------------------------------------------------------
// GEMM: Y[M][N] = X[M][K] @ W[N][K]^T   (K = N = DM = 1024)
// BM=BN=128, BK=16, 256 threads, 8x8 microtile per thread.
// Both operands are K-contiguous -> transpose on smem store, float4 loads.
// ---------------------------------------------------------------------------
__global__ __launch_bounds__(256) void gemm_xwt(
    const float* __restrict__ X, const float* __restrict__ W,
    float* __restrict__ Y)
{
    __shared__ __align__(16) float As[16][132];   // [k][m], padded
    __shared__ __align__(16) float Bs[16][132];   // [k][n], padded

    const int tid = threadIdx.x;
    const int tx  = tid & 15;       // 0..15 -> n direction
    const int ty  = tid >> 4;       // 0..15 -> m direction
    const int bm  = blockIdx.y;
    const int bn  = blockIdx.x;

    const float* Xg = X + (size_t)(bm * 128) * DM;
    const float* Wg = W + (size_t)(bn * 128) * DM;

    float acc[8][8];
#pragma unroll
    for (int i = 0; i < 8; i++)
#pragma unroll
        for (int j = 0; j < 8; j++) acc[i][j] = 0.f;

    for (int kt = 0; kt < DM; kt += 16) {
#pragma unroll
        for (int it = 0; it < 2; it++) {
            int idx = tid + it * 256;        // 0..511
            int row = idx >> 2;              // 0..127
            int c4  = (idx & 3) * 4;         // 0,4,8,12
            float4 va = *reinterpret_cast<const float4*>(Xg + (size_t)row * DM + kt + c4);
            As[c4 + 0][row] = va.x; As[c4 + 1][row] = va.y;
            As[c4 + 2][row] = va.z; As[c4 + 3][row] = va.w;
            float4 vb = *reinterpret_cast<const float4*>(Wg + (size_t)row * DM + kt + c4);
            Bs[c4 + 0][row] = vb.x; Bs[c4 + 1][row] = vb.y;
            Bs[c4 + 2][row] = vb.z; Bs[c4 + 3][row] = vb.w;
        }
        __syncthreads();

#pragma unroll
        for (int k = 0; k < 16; k++) {
            float a[8], b[8];
            *reinterpret_cast<float4*>(a)     = *reinterpret_cast<float4*>(&As[k][ty * 8]);
            *reinterpret_cast<float4*>(a + 4) = *reinterpret_cast<float4*>(&As[k][ty * 8 + 4]);
            *reinterpret_cast<float4*>(b)     = *reinterpret_cast<float4*>(&Bs[k][tx * 8]);
            *reinterpret_cast<float4*>(b + 4) = *reinterpret_cast<float4*>(&Bs[k][tx * 8 + 4]);
#pragma unroll
            for (int i = 0; i < 8; i++)
#pragma unroll
                for (int j = 0; j < 8; j++)
                    acc[i][j] = fmaf(a[i], b[j], acc[i][j]);
        }
        __syncthreads();
    }

#pragma unroll
    for (int i = 0; i < 8; i++) {
        size_t row = (size_t)(bm * 128 + ty * 8 + i);
        float* yp = Y + row * DM + bn * 128 + tx * 8;
        *reinterpret_cast<float4*>(yp)     = make_float4(acc[i][0], acc[i][1], acc[i][2], acc[i][3]);
        *reinterpret_cast<float4*>(yp + 4) = make_float4(acc[i][4], acc[i][5], acc[i][6], acc[i][7]);
    }
}

// ---------------------------------------------------------------------------
// Flash attention, fp32. One CTA = (head h, 64-row Q block).
// Br = Bc = 64, d = 64, 256 threads, 4x4 microtile per thread.
// Online softmax; P tile shares smem with K tile. Scale folded into Q load.
// ---------------------------------------------------------------------------
__global__ __launch_bounds__(256) void flash_attn(
    const float* __restrict__ Q, const float* __restrict__ K,
    const float* __restrict__ V, float* __restrict__ O)
{
    extern __shared__ __align__(16) float sm[];
    float* Qs  = sm;                 // [64][68] transposed: Qs[d][i]
    float* KPs = sm + 64 * 68;       // [64][68] K transposed Ks[d][j]; later P^T: Ps[j][i]
    float* Vs  = sm + 2 * 64 * 68;   // [64][68] Vs[r][c]

    const int tid = threadIdx.x;
    const int tx  = tid & 15;        // column group (j / c)
    const int ty  = tid >> 4;        // row group (i)
    const int h   = blockIdx.x;
    const int qb  = blockIdx.y;
    const float scale = 0.125f;      // 1/sqrt(64)

    // Load Q tile (64 x 64) transposed, scale folded in.
#pragma unroll
    for (int it = 0; it < 4; it++) {
        int idx = tid + it * 256;            // 0..1023
        int r   = idx >> 4;                  // 0..63
        int c4  = (idx & 15) * 4;            // 0..60
        float4 v = *reinterpret_cast<const float4*>(
            Q + (size_t)(qb * 64 + r) * DM + h * DK + c4);
        Qs[(c4 + 0) * 68 + r] = v.x * scale;
        Qs[(c4 + 1) * 68 + r] = v.y * scale;
        Qs[(c4 + 2) * 68 + r] = v.z * scale;
        Qs[(c4 + 3) * 68 + r] = v.w * scale;
    }

    float o[4][4];
    float m[4], l[4];
#pragma unroll
    for (int a = 0; a < 4; a++) {
        m[a] = -1e30f; l[a] = 0.f;
#pragma unroll
        for (int c = 0; c < 4; c++) o[a][c] = 0.f;
    }

    for (int kv = 0; kv < SEQ / 64; kv++) {
        __syncthreads();   // previous iteration done reading KPs/Vs (and Qs load on iter 0)

        // Load K tile transposed + V tile straight.
#pragma unroll
        for (int it = 0; it < 4; it++) {
            int idx = tid + it * 256;
            int r   = idx >> 4;
            int c4  = (idx & 15) * 4;
            float4 kvv = *reinterpret_cast<const float4*>(
                K + (size_t)(kv * 64 + r) * DM + h * DK + c4);
            KPs[(c4 + 0) * 68 + r] = kvv.x;
            KPs[(c4 + 1) * 68 + r] = kvv.y;
            KPs[(c4 + 2) * 68 + r] = kvv.z;
            KPs[(c4 + 3) * 68 + r] = kvv.w;
            float4 vv = *reinterpret_cast<const float4*>(
                V + (size_t)(kv * 64 + r) * DM + h * DK + c4);
            *reinterpret_cast<float4*>(&Vs[r * 68 + c4]) = vv;
        }
        __syncthreads();

        // S = (Q*scale) @ K^T  -- 4x4 fragment
        float s[4][4];
#pragma unroll
        for (int a = 0; a < 4; a++)
#pragma unroll
            for (int b = 0; b < 4; b++) s[a][b] = 0.f;

#pragma unroll 16
        for (int d = 0; d < 64; d++) {
            float qa[4], kb[4];
            *reinterpret_cast<float4*>(qa) = *reinterpret_cast<float4*>(&Qs[d * 68 + ty * 4]);
            *reinterpret_cast<float4*>(kb) = *reinterpret_cast<float4*>(&KPs[d * 68 + tx * 4]);
#pragma unroll
            for (int a = 0; a < 4; a++)
#pragma unroll
                for (int b = 0; b < 4; b++)
                    s[a][b] = fmaf(qa[a], kb[b], s[a][b]);
        }

        // Online softmax per row (allreduce across the 16 tx lanes, same warp half)
#pragma unroll
        for (int a = 0; a < 4; a++) {
            float mx = fmaxf(fmaxf(s[a][0], s[a][1]), fmaxf(s[a][2], s[a][3]));
#pragma unroll
            for (int off = 1; off < 16; off <<= 1)
                mx = fmaxf(mx, __shfl_xor_sync(0xffffffffu, mx, off));
            float mn   = fmaxf(m[a], mx);
            float corr = __expf(m[a] - mn);
            float rs   = 0.f;
#pragma unroll
            for (int b = 0; b < 4; b++) {
                s[a][b] = __expf(s[a][b] - mn);
                rs += s[a][b];
            }
#pragma unroll
            for (int off = 1; off < 16; off <<= 1)
                rs += __shfl_xor_sync(0xffffffffu, rs, off);
            l[a] = l[a] * corr + rs;
            m[a] = mn;
#pragma unroll
            for (int c = 0; c < 4; c++) o[a][c] *= corr;
        }

        __syncthreads();   // everyone done reading K from KPs

        // Write P transposed into KPs: Ps[j][i] = P[i][j]
#pragma unroll
        for (int a = 0; a < 4; a++)
#pragma unroll
            for (int b = 0; b < 4; b++)
                KPs[(tx * 4 + b) * 68 + ty * 4 + a] = s[a][b];

        __syncthreads();

        // O += P @ V
#pragma unroll 16
        for (int r = 0; r < 64; r++) {
            float pa[4], va[4];
            *reinterpret_cast<float4*>(pa) = *reinterpret_cast<float4*>(&KPs[r * 68 + ty * 4]);
            *reinterpret_cast<float4*>(va) = *reinterpret_cast<float4*>(&Vs[r * 68 + tx * 4]);
#pragma unroll
            for (int a = 0; a < 4; a++)
#pragma unroll
                for (int c = 0; c < 4; c++)
                    o[a][c] = fmaf(pa[a], va[c], o[a][c]);
        }
    }

    // Normalize and store
#pragma unroll
    for (int a = 0; a < 4; a++) {
        float inv = 1.f / l[a];
        float4 ov = make_float4(o[a][0] * inv, o[a][1] * inv, o[a][2] * inv, o[a][3] * inv);
        *reinterpret_cast<float4*>(
            O + (size_t)(qb * 64 + ty * 4 + a) * DM + h * DK + tx * 4) = ov;
    }
}

// ---------------------------------------------------------------------------
extern "C" void kernel_launch(void* const* d_in, const int* in_sizes, int n_in,
                              void* d_out, int out_size)
{
    const float* query = (const float*)d_in[0];
    const float* key_t = (const float*)d_in[1];
    const float* value = (const float*)d_in[2];
    const float* w_q   = (const float*)d_in[3];
    const float* w_k   = (const float*)d_in[4];
    const float* w_v   = (const float*)d_in[5];
    const float* w_o   = (const float*)d_in[6];
    float* out = (float*)d_out;

    float *Qp, *Kp, *Vp, *Op;
    cudaGetSymbolAddress((void**)&Qp, g_Q);
    cudaGetSymbolAddress((void**)&Kp, g_K);
    cudaGetSymbolAddress((void**)&Vp, g_V);
    cudaGetSymbolAddress((void**)&Op, g_O);

    const int smem_attn = 3 * 64 * 68 * (int)sizeof(float);   // 52224 B
    cudaFuncSetAttribute(flash_attn, cudaFuncAttributeMaxDynamicSharedMemorySize, smem_attn);

    dim3 ggrid(DM / 128, SEQ / 128);   // (8, 32)
    gemm_xwt<<<ggrid, 256>>>(query, w_q, Qp);
    gemm_xwt<<<ggrid, 256>>>(key_t, w_k, Kp);
    gemm_xwt<<<ggrid, 256>>>(value, w_v, Vp);

    dim3 agrid(NH, SEQ / 64);          // (16, 64)
    flash_attn<<<agrid, 256, smem_attn>>>(Qp, Kp, Vp, Op);

    gemm_xwt<<<ggrid, 256>>>(Op, w_o, out);
}

// round 6
// speedup vs baseline: 1.2525x; 1.2525x over previous
#include <cuda_runtime.h>
#include <cuda_bf16.h>
#include <cstdint>
#include <math.h>

#define SEQ 4096
#define DM  1024
#define NH  16
#define DK  64

// ---------------------------------------------------------------------------
// Scratch (__device__ globals: allocation-guard safe)
// ---------------------------------------------------------------------------
__device__ float g_Q[SEQ * DM];
__device__ float g_K[SEQ * DM];
__device__ float g_V[SEQ * DM];
__device__ float g_O[SEQ * DM];

// bf16 hi/lo splits of activations and weights
__device__ __nv_bfloat16 g_xqh[SEQ * DM], g_xql[SEQ * DM];
__device__ __nv_bfloat16 g_xkh[SEQ * DM], g_xkl[SEQ * DM];
__device__ __nv_bfloat16 g_xvh[SEQ * DM], g_xvl[SEQ * DM];
__device__ __nv_bfloat16 g_oh [SEQ * DM], g_ol [SEQ * DM];
__device__ __nv_bfloat16 g_wqh[DM * DM],  g_wql[DM * DM];
__device__ __nv_bfloat16 g_wkh[DM * DM],  g_wkl[DM * DM];
__device__ __nv_bfloat16 g_wvh[DM * DM],  g_wvl[DM * DM];
__device__ __nv_bfloat16 g_woh[DM * DM],  g_wol[DM * DM];

// ---------------------------------------------------------------------------
// PTX helpers: mma.sync (HMMA) + ldmatrix — valid at compute_103
// ---------------------------------------------------------------------------
__device__ __forceinline__ uint32_t smem_u32(const void* p) {
    uint32_t a;
    asm("{ .reg .u64 t; cvta.to.shared.u64 t, %1; cvt.u32.u64 %0, t; }" : "=r"(a) : "l"(p));
    return a;
}

__device__ __forceinline__ void ldsm_x4(uint32_t* r, uint32_t addr) {
    asm volatile("ldmatrix.sync.aligned.m8n8.x4.shared.b16 {%0,%1,%2,%3}, [%4];"
                 : "=r"(r[0]), "=r"(r[1]), "=r"(r[2]), "=r"(r[3]) : "r"(addr));
}
__device__ __forceinline__ void ldsm_x2(uint32_t* r, uint32_t addr) {
    asm volatile("ldmatrix.sync.aligned.m8n8.x2.shared.b16 {%0,%1}, [%2];"
                 : "=r"(r[0]), "=r"(r[1]) : "r"(addr));
}

// D(fp32) += A(bf16,row) * B(bf16,col), m16n8k16
__device__ __forceinline__ void mma_bf16(float* c, const uint32_t* a, const uint32_t* b) {
    asm volatile(
        "mma.sync.aligned.m16n8k16.row.col.f32.bf16.bf16.f32 "
        "{%0,%1,%2,%3}, {%4,%5,%6,%7}, {%8,%9}, {%0,%1,%2,%3};"
        : "+f"(c[0]), "+f"(c[1]), "+f"(c[2]), "+f"(c[3])
        : "r"(a[0]), "r"(a[1]), "r"(a[2]), "r"(a[3]), "r"(b[0]), "r"(b[1]));
}

// ---------------------------------------------------------------------------
// fp32 -> bf16 hi/lo split:  x = hi + lo + O(2^-17 x)
// ---------------------------------------------------------------------------
__global__ __launch_bounds__(256) void split_bf16(
    const float* __restrict__ x, __nv_bfloat16* __restrict__ h,
    __nv_bfloat16* __restrict__ l, int n)
{
    int i = (blockIdx.x * 256 + threadIdx.x) * 4;
    if (i >= n) return;
    float4 v = *reinterpret_cast<const float4*>(x + i);
    __nv_bfloat16 h0 = __float2bfloat16(v.x), h1 = __float2bfloat16(v.y);
    __nv_bfloat16 h2 = __float2bfloat16(v.z), h3 = __float2bfloat16(v.w);
    __nv_bfloat16 l0 = __float2bfloat16(v.x - __bfloat162float(h0));
    __nv_bfloat16 l1 = __float2bfloat16(v.y - __bfloat162float(h1));
    __nv_bfloat16 l2 = __float2bfloat16(v.z - __bfloat162float(h2));
    __nv_bfloat16 l3 = __float2bfloat16(v.w - __bfloat162float(h3));
    *reinterpret_cast<__nv_bfloat162*>(h + i)     = __nv_bfloat162(h0, h1);
    *reinterpret_cast<__nv_bfloat162*>(h + i + 2) = __nv_bfloat162(h2, h3);
    *reinterpret_cast<__nv_bfloat162*>(l + i)     = __nv_bfloat162(l0, l1);
    *reinterpret_cast<__nv_bfloat162*>(l + i + 2) = __nv_bfloat162(l2, l3);
}

// ---------------------------------------------------------------------------
// HMMA GEMM: Y[4096x1024] = A[4096x1024] @ B[1024x1024]^T, both K-major bf16.
// D = Ah@Bh + Ah@Bl + Al@Bh  (3xBF16, fp32 register accumulators).
// CTA tile 128x128 (8 warps of 64x32), BK=32, smem LD=40 bf16 (conflict-free).
// ---------------------------------------------------------------------------
#define GLD 40   // smem row pitch in bf16 (80 B)

__global__ __launch_bounds__(256) void gemm_mma(
    const __nv_bfloat16* __restrict__ Ah, const __nv_bfloat16* __restrict__ Al,
    const __nv_bfloat16* __restrict__ Bh, const __nv_bfloat16* __restrict__ Bl,
    float* __restrict__ Y)
{
    extern __shared__ __align__(16) __nv_bfloat16 smg[];
    __nv_bfloat16* sAh = smg;                 // [128][GLD]
    __nv_bfloat16* sAl = smg + 128 * GLD;
    __nv_bfloat16* sBh = smg + 2 * 128 * GLD;
    __nv_bfloat16* sBl = smg + 3 * 128 * GLD;

    const int tid  = threadIdx.x;
    const int lane = tid & 31;
    const int wid  = tid >> 5;        // 0..7
    const int wm   = wid >> 2;        // 0..1  (64-row slab)
    const int wn   = wid & 3;         // 0..3  (32-col slab)
    const int bm   = blockIdx.y, bn = blockIdx.x;

    const uint32_t uAh = smem_u32(sAh), uAl = smem_u32(sAl);
    const uint32_t uBh = smem_u32(sBh), uBl = smem_u32(sBl);

    float acc[4][4][4];
#pragma unroll
    for (int i = 0; i < 4; i++)
#pragma unroll
        for (int j = 0; j < 4; j++)
#pragma unroll
            for (int k = 0; k < 4; k++) acc[i][j][k] = 0.f;

    // ldmatrix source addresses (lane-dependent, hoisted)
    // A x4: row = wm*64 + i*16 + (lane&15), col = s*16 + (lane>>4)*8
    const int a_r = (lane & 15), a_c = (lane >> 4) * 8;
    // B x2: row(n) = wn*32 + j*8 + (lane&7), col(k) = s*16 + ((lane>>3)&1)*8
    const int b_r = (lane & 7),  b_c = ((lane >> 3) & 1) * 8;

    for (int kt = 0; kt < DM; kt += 32) {
        // ---- load 4 tiles of 128 x 32 bf16 ----
#pragma unroll
        for (int it = 0; it < 2; it++) {
            int idx = tid + it * 256;          // 0..511
            int r = idx >> 2;                  // 0..127
            int c = (idx & 3) * 8;             // bf16 col: 0,8,16,24
            size_t ga = (size_t)(bm * 128 + r) * DM + kt + c;
            size_t gb = (size_t)(bn * 128 + r) * DM + kt + c;
            *reinterpret_cast<uint4*>(sAh + r * GLD + c) = *reinterpret_cast<const uint4*>(Ah + ga);
            *reinterpret_cast<uint4*>(sAl + r * GLD + c) = *reinterpret_cast<const uint4*>(Al + ga);
            *reinterpret_cast<uint4*>(sBh + r * GLD + c) = *reinterpret_cast<const uint4*>(Bh + gb);
            *reinterpret_cast<uint4*>(sBl + r * GLD + c) = *reinterpret_cast<const uint4*>(Bl + gb);
        }
        __syncthreads();

        // ---- compute: 2 k16 steps ----
#pragma unroll
        for (int s = 0; s < 2; s++) {
            uint32_t ah[4][4], al[4][4], bh[4][2], bl[4][2];
#pragma unroll
            for (int i = 0; i < 4; i++) {
                uint32_t off = (uint32_t)(((wm * 64 + i * 16 + a_r) * GLD + s * 16 + a_c) * 2);
                ldsm_x4(ah[i], uAh + off);
                ldsm_x4(al[i], uAl + off);
            }
#pragma unroll
            for (int j = 0; j < 4; j++) {
                uint32_t off = (uint32_t)(((wn * 32 + j * 8 + b_r) * GLD + s * 16 + b_c) * 2);
                ldsm_x2(bh[j], uBh + off);
                ldsm_x2(bl[j], uBl + off);
            }
#pragma unroll
            for (int i = 0; i < 4; i++)
#pragma unroll
                for (int j = 0; j < 4; j++) {
                    mma_bf16(acc[i][j], ah[i], bh[j]);
                    mma_bf16(acc[i][j], ah[i], bl[j]);
                    mma_bf16(acc[i][j], al[i], bh[j]);
                }
        }
        __syncthreads();
    }

    // ---- epilogue: c frag -> gmem fp32 ----
    const int g = lane >> 2, t = lane & 3;
#pragma unroll
    for (int i = 0; i < 4; i++) {
        int row0 = bm * 128 + wm * 64 + i * 16 + g;
#pragma unroll
        for (int j = 0; j < 4; j++) {
            int col = bn * 128 + wn * 32 + j * 8 + 2 * t;
            *reinterpret_cast<float2*>(Y + (size_t)row0 * DM + col) =
                make_float2(acc[i][j][0], acc[i][j][1]);
            *reinterpret_cast<float2*>(Y + (size_t)(row0 + 8) * DM + col) =
                make_float2(acc[i][j][2], acc[i][j][3]);
        }
    }
}

// ---------------------------------------------------------------------------
// Flash attention, fp32. One CTA = (head h, 128-row Q block). Br=128, Bc=64.
// 256 threads, 8x4 microtile.
// ---------------------------------------------------------------------------
__global__ __launch_bounds__(256) void flash_attn(
    const float* __restrict__ Q, const float* __restrict__ K,
    const float* __restrict__ V, float* __restrict__ O)
{
    extern __shared__ __align__(16) float sm[];
    float* Qs  = sm;                   // [64 d][132] transposed: Qs[d][i], i<128
    float* KPs = sm + 64 * 132;        // K^T [64 d][132] (j<64); later P^T [64 j][132]
    float* Vs  = sm + 2 * 64 * 132;    // [64 r][68]

    const int tid = threadIdx.x;
    const int tx  = tid & 15;
    const int ty  = tid >> 4;
    const int h   = blockIdx.x;
    const int qb  = blockIdx.y;
    const float scale = 0.125f;

#pragma unroll
    for (int it = 0; it < 8; it++) {
        int idx = tid + it * 256;
        int r   = idx >> 4;
        int c4  = (idx & 15) * 4;
        float4 v = *reinterpret_cast<const float4*>(
            Q + (size_t)(qb * 128 + r) * DM + h * DK + c4);
        Qs[(c4 + 0) * 132 + r] = v.x * scale;
        Qs[(c4 + 1) * 132 + r] = v.y * scale;
        Qs[(c4 + 2) * 132 + r] = v.z * scale;
        Qs[(c4 + 3) * 132 + r] = v.w * scale;
    }

    float o[8][4];
    float m[8], l[8];
#pragma unroll
    for (int a = 0; a < 8; a++) {
        m[a] = -1e30f; l[a] = 0.f;
#pragma unroll
        for (int c = 0; c < 4; c++) o[a][c] = 0.f;
    }

    for (int kv = 0; kv < SEQ / 64; kv++) {
        __syncthreads();
#pragma unroll
        for (int it = 0; it < 4; it++) {
            int idx = tid + it * 256;
            int r   = idx >> 4;
            int c4  = (idx & 15) * 4;
            float4 kvv = *reinterpret_cast<const float4*>(
                K + (size_t)(kv * 64 + r) * DM + h * DK + c4);
            KPs[(c4 + 0) * 132 + r] = kvv.x;
            KPs[(c4 + 1) * 132 + r] = kvv.y;
            KPs[(c4 + 2) * 132 + r] = kvv.z;
            KPs[(c4 + 3) * 132 + r] = kvv.w;
            float4 vv = *reinterpret_cast<const float4*>(
                V + (size_t)(kv * 64 + r) * DM + h * DK + c4);
            *reinterpret_cast<float4*>(&Vs[r * 68 + c4]) = vv;
        }
        __syncthreads();

        float s[8][4];
#pragma unroll
        for (int a = 0; a < 8; a++)
#pragma unroll
            for (int b = 0; b < 4; b++) s[a][b] = 0.f;

#pragma unroll 16
        for (int d = 0; d < 64; d++) {
            float qa[8], kb[4];
            *reinterpret_cast<float4*>(qa)     = *reinterpret_cast<float4*>(&Qs[d * 132 + ty * 8]);
            *reinterpret_cast<float4*>(qa + 4) = *reinterpret_cast<float4*>(&Qs[d * 132 + ty * 8 + 4]);
            *reinterpret_cast<float4*>(kb)     = *reinterpret_cast<float4*>(&KPs[d * 132 + tx * 4]);
#pragma unroll
            for (int a = 0; a < 8; a++)
#pragma unroll
                for (int b = 0; b < 4; b++)
                    s[a][b] = fmaf(qa[a], kb[b], s[a][b]);
        }

#pragma unroll
        for (int a = 0; a < 8; a++) {
            float mx = fmaxf(fmaxf(s[a][0], s[a][1]), fmaxf(s[a][2], s[a][3]));
#pragma unroll
            for (int off = 1; off < 16; off <<= 1)
                mx = fmaxf(mx, __shfl_xor_sync(0xffffffffu, mx, off));
            float mn   = fmaxf(m[a], mx);
            float corr = __expf(m[a] - mn);
            float rs   = 0.f;
#pragma unroll
            for (int b = 0; b < 4; b++) {
                s[a][b] = __expf(s[a][b] - mn);
                rs += s[a][b];
            }
#pragma unroll
            for (int off = 1; off < 16; off <<= 1)
                rs += __shfl_xor_sync(0xffffffffu, rs, off);
            l[a] = l[a] * corr + rs;
            m[a] = mn;
#pragma unroll
            for (int c = 0; c < 4; c++) o[a][c] *= corr;
        }

        __syncthreads();
#pragma unroll
        for (int a = 0; a < 8; a++)
#pragma unroll
            for (int b = 0; b < 4; b++)
                KPs[(tx * 4 + b) * 132 + ty * 8 + a] = s[a][b];
        __syncthreads();

#pragma unroll 16
        for (int r = 0; r < 64; r++) {
            float pa[8], va[4];
            *reinterpret_cast<float4*>(pa)     = *reinterpret_cast<float4*>(&KPs[r * 132 + ty * 8]);
            *reinterpret_cast<float4*>(pa + 4) = *reinterpret_cast<float4*>(&KPs[r * 132 + ty * 8 + 4]);
            *reinterpret_cast<float4*>(va)     = *reinterpret_cast<float4*>(&Vs[r * 68 + tx * 4]);
#pragma unroll
            for (int a = 0; a < 8; a++)
#pragma unroll
                for (int c = 0; c < 4; c++)
                    o[a][c] = fmaf(pa[a], va[c], o[a][c]);
        }
    }

#pragma unroll
    for (int a = 0; a < 8; a++) {
        float inv = 1.f / l[a];
        float4 ov = make_float4(o[a][0] * inv, o[a][1] * inv, o[a][2] * inv, o[a][3] * inv);
        *reinterpret_cast<float4*>(
            O + (size_t)(qb * 128 + ty * 8 + a) * DM + h * DK + tx * 4) = ov;
    }
}

// ---------------------------------------------------------------------------
extern "C" void kernel_launch(void* const* d_in, const int* in_sizes, int n_in,
                              void* d_out, int out_size)
{
    const float* query = (const float*)d_in[0];
    const float* key_t = (const float*)d_in[1];
    const float* value = (const float*)d_in[2];
    const float* w_q   = (const float*)d_in[3];
    const float* w_k   = (const float*)d_in[4];
    const float* w_v   = (const float*)d_in[5];
    const float* w_o   = (const float*)d_in[6];
    float* out = (float*)d_out;

    float *Qp, *Kp, *Vp, *Op;
    cudaGetSymbolAddress((void**)&Qp, g_Q);
    cudaGetSymbolAddress((void**)&Kp, g_K);
    cudaGetSymbolAddress((void**)&Vp, g_V);
    cudaGetSymbolAddress((void**)&Op, g_O);
    __nv_bfloat16 *xqh, *xql, *xkh, *xkl, *xvh, *xvl, *oh, *ol;
    __nv_bfloat16 *wqh, *wql, *wkh, *wkl, *wvh, *wvl, *woh, *wol;
    cudaGetSymbolAddress((void**)&xqh, g_xqh); cudaGetSymbolAddress((void**)&xql, g_xql);
    cudaGetSymbolAddress((void**)&xkh, g_xkh); cudaGetSymbolAddress((void**)&xkl, g_xkl);
    cudaGetSymbolAddress((void**)&xvh, g_xvh); cudaGetSymbolAddress((void**)&xvl, g_xvl);
    cudaGetSymbolAddress((void**)&oh,  g_oh);  cudaGetSymbolAddress((void**)&ol,  g_ol);
    cudaGetSymbolAddress((void**)&wqh, g_wqh); cudaGetSymbolAddress((void**)&wql, g_wql);
    cudaGetSymbolAddress((void**)&wkh, g_wkh); cudaGetSymbolAddress((void**)&wkl, g_wkl);
    cudaGetSymbolAddress((void**)&wvh, g_wvh); cudaGetSymbolAddress((void**)&wvl, g_wvl);
    cudaGetSymbolAddress((void**)&woh, g_woh); cudaGetSymbolAddress((void**)&wol, g_wol);

    const int smem_gemm = 4 * 128 * GLD * (int)sizeof(__nv_bfloat16);          // 40960 B
    const int smem_attn = (2 * 64 * 132 + 64 * 68) * (int)sizeof(float);       // 84992 B
    cudaFuncSetAttribute(gemm_mma,   cudaFuncAttributeMaxDynamicSharedMemorySize, smem_gemm);
    cudaFuncSetAttribute(flash_attn, cudaFuncAttributeMaxDynamicSharedMemorySize, smem_attn);

    const int nAct = SEQ * DM, nW = DM * DM;
    split_bf16<<<nAct / 1024, 256>>>(query, xqh, xql, nAct);
    split_bf16<<<nAct / 1024, 256>>>(key_t, xkh, xkl, nAct);
    split_bf16<<<nAct / 1024, 256>>>(value, xvh, xvl, nAct);
    split_bf16<<<nW / 1024, 256>>>(w_q, wqh, wql, nW);
    split_bf16<<<nW / 1024, 256>>>(w_k, wkh, wkl, nW);
    split_bf16<<<nW / 1024, 256>>>(w_v, wvh, wvl, nW);
    split_bf16<<<nW / 1024, 256>>>(w_o, woh, wol, nW);

    dim3 ggrid(DM / 128, SEQ / 128);   // (8, 32)
    gemm_mma<<<ggrid, 256, smem_gemm>>>(xqh, xql, wqh, wql, Qp);
    gemm_mma<<<ggrid, 256, smem_gemm>>>(xkh, xkl, wkh, wkl, Kp);
    gemm_mma<<<ggrid, 256, smem_gemm>>>(xvh, xvl, wvh, wvl, Vp);

    dim3 agrid(NH, SEQ / 128);         // (16, 32)
    flash_attn<<<agrid, 256, smem_attn>>>(Qp, Kp, Vp, Op);

    split_bf16<<<nAct / 1024, 256>>>(Op, oh, ol, nAct);
    gemm_mma<<<ggrid, 256, smem_gemm>>>(oh, ol, woh, wol, out);
}

// round 7
// speedup vs baseline: 2.0697x; 1.6524x over previous
#include <cuda_runtime.h>
#include <cuda_bf16.h>
#include <cstdint>
#include <math.h>

#define SEQ 4096
#define DM  1024
#define NH  16
#define DK  64

// ---------------------------------------------------------------------------
// Scratch (__device__ globals: allocation-guard safe)
// ---------------------------------------------------------------------------
__device__ float g_Q[SEQ * DM];
__device__ float g_K[SEQ * DM];
__device__ float g_V[SEQ * DM];
__device__ float g_O[SEQ * DM];

__device__ __nv_bfloat16 g_xqh[SEQ * DM], g_xql[SEQ * DM];
__device__ __nv_bfloat16 g_xkh[SEQ * DM], g_xkl[SEQ * DM];
__device__ __nv_bfloat16 g_xvh[SEQ * DM], g_xvl[SEQ * DM];
__device__ __nv_bfloat16 g_oh [SEQ * DM], g_ol [SEQ * DM];
__device__ __nv_bfloat16 g_wqh[DM * DM],  g_wql[DM * DM];
__device__ __nv_bfloat16 g_wkh[DM * DM],  g_wkl[DM * DM];
__device__ __nv_bfloat16 g_wvh[DM * DM],  g_wvl[DM * DM];
__device__ __nv_bfloat16 g_woh[DM * DM],  g_wol[DM * DM];

// ---------------------------------------------------------------------------
// PTX helpers: mma.sync (HMMA) + ldmatrix — valid at compute_103
// ---------------------------------------------------------------------------
__device__ __forceinline__ uint32_t smem_u32(const void* p) {
    uint32_t a;
    asm("{ .reg .u64 t; cvta.to.shared.u64 t, %1; cvt.u32.u64 %0, t; }" : "=r"(a) : "l"(p));
    return a;
}
__device__ __forceinline__ void ldsm_x4(uint32_t* r, uint32_t addr) {
    asm volatile("ldmatrix.sync.aligned.m8n8.x4.shared.b16 {%0,%1,%2,%3}, [%4];"
                 : "=r"(r[0]), "=r"(r[1]), "=r"(r[2]), "=r"(r[3]) : "r"(addr));
}
__device__ __forceinline__ void ldsm_x2(uint32_t* r, uint32_t addr) {
    asm volatile("ldmatrix.sync.aligned.m8n8.x2.shared.b16 {%0,%1}, [%2];"
                 : "=r"(r[0]), "=r"(r[1]) : "r"(addr));
}
__device__ __forceinline__ void mma_bf16(float* c, const uint32_t* a, const uint32_t* b) {
    asm volatile(
        "mma.sync.aligned.m16n8k16.row.col.f32.bf16.bf16.f32 "
        "{%0,%1,%2,%3}, {%4,%5,%6,%7}, {%8,%9}, {%0,%1,%2,%3};"
        : "+f"(c[0]), "+f"(c[1]), "+f"(c[2]), "+f"(c[3])
        : "r"(a[0]), "r"(a[1]), "r"(a[2]), "r"(a[3]), "r"(b[0]), "r"(b[1]));
}

// pack two floats into bf16x2 hi reg + bf16x2 lo-residual reg
__device__ __forceinline__ void split_pack2(float x, float y, uint32_t& hi, uint32_t& lo) {
    __nv_bfloat162 h2 = __floats2bfloat162_rn(x, y);
    float rx = x - __bfloat162float(h2.x);
    float ry = y - __bfloat162float(h2.y);
    __nv_bfloat162 l2 = __floats2bfloat162_rn(rx, ry);
    hi = *reinterpret_cast<uint32_t*>(&h2);
    lo = *reinterpret_cast<uint32_t*>(&l2);
}

// ---------------------------------------------------------------------------
// fp32 -> bf16 hi/lo split (for GEMM operands)
// ---------------------------------------------------------------------------
__global__ __launch_bounds__(256) void split_bf16(
    const float* __restrict__ x, __nv_bfloat16* __restrict__ h,
    __nv_bfloat16* __restrict__ l, int n)
{
    int i = (blockIdx.x * 256 + threadIdx.x) * 4;
    if (i >= n) return;
    float4 v = *reinterpret_cast<const float4*>(x + i);
    uint32_t h01, l01, h23, l23;
    split_pack2(v.x, v.y, h01, l01);
    split_pack2(v.z, v.w, h23, l23);
    *reinterpret_cast<uint32_t*>(h + i)     = h01;
    *reinterpret_cast<uint32_t*>(h + i + 2) = h23;
    *reinterpret_cast<uint32_t*>(l + i)     = l01;
    *reinterpret_cast<uint32_t*>(l + i + 2) = l23;
}

// ---------------------------------------------------------------------------
// HMMA GEMM: Y = A @ B^T, 3xBF16 split. CTA 128x128, 8 warps 64x32, BK=32.
// ---------------------------------------------------------------------------
#define GLD 40

__global__ __launch_bounds__(256) void gemm_mma(
    const __nv_bfloat16* __restrict__ Ah, const __nv_bfloat16* __restrict__ Al,
    const __nv_bfloat16* __restrict__ Bh, const __nv_bfloat16* __restrict__ Bl,
    float* __restrict__ Y)
{
    extern __shared__ __align__(16) __nv_bfloat16 smg[];
    __nv_bfloat16* sAh = smg;
    __nv_bfloat16* sAl = smg + 128 * GLD;
    __nv_bfloat16* sBh = smg + 2 * 128 * GLD;
    __nv_bfloat16* sBl = smg + 3 * 128 * GLD;

    const int tid  = threadIdx.x;
    const int lane = tid & 31;
    const int wid  = tid >> 5;
    const int wm   = wid >> 2;
    const int wn   = wid & 3;
    const int bm   = blockIdx.y, bn = blockIdx.x;

    const uint32_t uAh = smem_u32(sAh), uAl = smem_u32(sAl);
    const uint32_t uBh = smem_u32(sBh), uBl = smem_u32(sBl);

    float acc[4][4][4];
#pragma unroll
    for (int i = 0; i < 4; i++)
#pragma unroll
        for (int j = 0; j < 4; j++)
#pragma unroll
            for (int k = 0; k < 4; k++) acc[i][j][k] = 0.f;

    const int a_r = (lane & 15), a_c = (lane >> 4) * 8;
    const int b_r = (lane & 7),  b_c = ((lane >> 3) & 1) * 8;

    for (int kt = 0; kt < DM; kt += 32) {
#pragma unroll
        for (int it = 0; it < 2; it++) {
            int idx = tid + it * 256;
            int r = idx >> 2;
            int c = (idx & 3) * 8;
            size_t ga = (size_t)(bm * 128 + r) * DM + kt + c;
            size_t gb = (size_t)(bn * 128 + r) * DM + kt + c;
            *reinterpret_cast<uint4*>(sAh + r * GLD + c) = *reinterpret_cast<const uint4*>(Ah + ga);
            *reinterpret_cast<uint4*>(sAl + r * GLD + c) = *reinterpret_cast<const uint4*>(Al + ga);
            *reinterpret_cast<uint4*>(sBh + r * GLD + c) = *reinterpret_cast<const uint4*>(Bh + gb);
            *reinterpret_cast<uint4*>(sBl + r * GLD + c) = *reinterpret_cast<const uint4*>(Bl + gb);
        }
        __syncthreads();

#pragma unroll
        for (int s = 0; s < 2; s++) {
            uint32_t ah[4][4], al[4][4], bh[4][2], bl[4][2];
#pragma unroll
            for (int i = 0; i < 4; i++) {
                uint32_t off = (uint32_t)(((wm * 64 + i * 16 + a_r) * GLD + s * 16 + a_c) * 2);
                ldsm_x4(ah[i], uAh + off);
                ldsm_x4(al[i], uAl + off);
            }
#pragma unroll
            for (int j = 0; j < 4; j++) {
                uint32_t off = (uint32_t)(((wn * 32 + j * 8 + b_r) * GLD + s * 16 + b_c) * 2);
                ldsm_x2(bh[j], uBh + off);
                ldsm_x2(bl[j], uBl + off);
            }
#pragma unroll
            for (int i = 0; i < 4; i++)
#pragma unroll
                for (int j = 0; j < 4; j++) {
                    mma_bf16(acc[i][j], ah[i], bh[j]);
                    mma_bf16(acc[i][j], ah[i], bl[j]);
                    mma_bf16(acc[i][j], al[i], bh[j]);
                }
        }
        __syncthreads();
    }

    const int g = lane >> 2, t = lane & 3;
#pragma unroll
    for (int i = 0; i < 4; i++) {
        int row0 = bm * 128 + wm * 64 + i * 16 + g;
#pragma unroll
        for (int j = 0; j < 4; j++) {
            int col = bn * 128 + wn * 32 + j * 8 + 2 * t;
            *reinterpret_cast<float2*>(Y + (size_t)row0 * DM + col) =
                make_float2(acc[i][j][0], acc[i][j][1]);
            *reinterpret_cast<float2*>(Y + (size_t)(row0 + 8) * DM + col) =
                make_float2(acc[i][j][2], acc[i][j][3]);
        }
    }
}

// ---------------------------------------------------------------------------
// HMMA flash attention, 3xBF16 splits everywhere (QK^T and PV).
// CTA = (head, 128 Q rows); 8 warps x (16 rows x 64 cols); Bc = 64.
// Q hi/lo in smem (rows natural), K hi/lo natural [kv][d], V hi/lo
// TRANSPOSED [d][kv] so both are ldmatrix NT B-operands. P stays in regs:
// S C-fragments repack directly into PV A-fragments.
// ---------------------------------------------------------------------------
#define FP 72   // smem pitch in bf16 (144 B: 16B-aligned, ldmatrix conflict-free)

__global__ __launch_bounds__(256) void flash_mma(
    const float* __restrict__ Q, const float* __restrict__ K,
    const float* __restrict__ V, float* __restrict__ O)
{
    extern __shared__ __align__(16) __nv_bfloat16 sb[];
    __nv_bfloat16* sQh = sb;
    __nv_bfloat16* sQl = sQh + 128 * FP;
    __nv_bfloat16* sKh = sQl + 128 * FP;
    __nv_bfloat16* sKl = sKh + 64 * FP;
    __nv_bfloat16* sVh = sKl + 64 * FP;   // transposed: [d][kv]
    __nv_bfloat16* sVl = sVh + 64 * FP;

    const int tid  = threadIdx.x;
    const int lane = tid & 31;
    const int wid  = tid >> 5;            // warp rows: wid*16 .. +15
    const int g    = lane >> 2;           // 0..7
    const int t    = lane & 3;            // 0..3
    const int h    = blockIdx.x;
    const int qb   = blockIdx.y;

    const uint32_t uQh = smem_u32(sQh), uQl = smem_u32(sQl);
    const uint32_t uKh = smem_u32(sKh), uKl = smem_u32(sKl);
    const uint32_t uVh = smem_u32(sVh), uVl = smem_u32(sVl);

    const int a_r = (lane & 15), a_c = (lane >> 4) * 8;
    const int b_r = (lane & 7),  b_c = ((lane >> 3) & 1) * 8;

    // ---- load Q (128 x 64), scale folded, split to bf16 hi/lo ----
#pragma unroll
    for (int it = 0; it < 8; it++) {
        int idx = tid + it * 256;
        int r   = idx >> 4;
        int c4  = (idx & 15) * 4;
        float4 v = *reinterpret_cast<const float4*>(
            Q + (size_t)(qb * 128 + r) * DM + h * DK + c4);
        v.x *= 0.125f; v.y *= 0.125f; v.z *= 0.125f; v.w *= 0.125f;
        uint32_t h01, l01, h23, l23;
        split_pack2(v.x, v.y, h01, l01);
        split_pack2(v.z, v.w, h23, l23);
        *reinterpret_cast<uint32_t*>(sQh + r * FP + c4)     = h01;
        *reinterpret_cast<uint32_t*>(sQh + r * FP + c4 + 2) = h23;
        *reinterpret_cast<uint32_t*>(sQl + r * FP + c4)     = l01;
        *reinterpret_cast<uint32_t*>(sQl + r * FP + c4 + 2) = l23;
    }

    float o[8][4];
#pragma unroll
    for (int nf = 0; nf < 8; nf++)
#pragma unroll
        for (int k = 0; k < 4; k++) o[nf][k] = 0.f;
    float m0 = -1e30f, m1 = -1e30f, l0 = 0.f, l1 = 0.f;

    for (int kv = 0; kv < SEQ / 64; kv++) {
        __syncthreads();   // smem consumers of previous tile done (and Q store, iter 0)

        // ---- load K (natural) + V (transposed), split hi/lo ----
#pragma unroll
        for (int it = 0; it < 4; it++) {
            int idx = tid + it * 256;
            int r   = idx >> 4;                 // kv row 0..63
            int c4  = (idx & 15) * 4;           // d col
            float4 kvv = *reinterpret_cast<const float4*>(
                K + (size_t)(kv * 64 + r) * DM + h * DK + c4);
            uint32_t h01, l01, h23, l23;
            split_pack2(kvv.x, kvv.y, h01, l01);
            split_pack2(kvv.z, kvv.w, h23, l23);
            *reinterpret_cast<uint32_t*>(sKh + r * FP + c4)     = h01;
            *reinterpret_cast<uint32_t*>(sKh + r * FP + c4 + 2) = h23;
            *reinterpret_cast<uint32_t*>(sKl + r * FP + c4)     = l01;
            *reinterpret_cast<uint32_t*>(sKl + r * FP + c4 + 2) = l23;

            float4 vv = *reinterpret_cast<const float4*>(
                V + (size_t)(kv * 64 + r) * DM + h * DK + c4);
            float vf[4] = {vv.x, vv.y, vv.z, vv.w};
#pragma unroll
            for (int i = 0; i < 4; i++) {
                __nv_bfloat16 vh = __float2bfloat16(vf[i]);
                __nv_bfloat16 vl = __float2bfloat16(vf[i] - __bfloat162float(vh));
                sVh[(c4 + i) * FP + r] = vh;
                sVl[(c4 + i) * FP + r] = vl;
            }
        }
        __syncthreads();

        // ---- S = Q @ K^T (3xBF16), per-warp 16x64 ----
        float s[8][4];
#pragma unroll
        for (int nf = 0; nf < 8; nf++)
#pragma unroll
            for (int k = 0; k < 4; k++) s[nf][k] = 0.f;

#pragma unroll
        for (int kc = 0; kc < 4; kc++) {
            uint32_t ah[4], al[4];
            uint32_t aoff = (uint32_t)(((wid * 16 + a_r) * FP + kc * 16 + a_c) * 2);
            ldsm_x4(ah, uQh + aoff);
            ldsm_x4(al, uQl + aoff);
#pragma unroll
            for (int nf = 0; nf < 8; nf++) {
                uint32_t bh[2], bl[2];
                uint32_t boff = (uint32_t)(((nf * 8 + b_r) * FP + kc * 16 + b_c) * 2);
                ldsm_x2(bh, uKh + boff);
                ldsm_x2(bl, uKl + boff);
                mma_bf16(s[nf], ah, bh);
                mma_bf16(s[nf], ah, bl);
                mma_bf16(s[nf], al, bh);
            }
        }

        // ---- online softmax (rows g / g+8; quad reduce over t) ----
        float mx0 = -1e30f, mx1 = -1e30f;
#pragma unroll
        for (int nf = 0; nf < 8; nf++) {
            mx0 = fmaxf(mx0, fmaxf(s[nf][0], s[nf][1]));
            mx1 = fmaxf(mx1, fmaxf(s[nf][2], s[nf][3]));
        }
        mx0 = fmaxf(mx0, __shfl_xor_sync(0xffffffffu, mx0, 1));
        mx0 = fmaxf(mx0, __shfl_xor_sync(0xffffffffu, mx0, 2));
        mx1 = fmaxf(mx1, __shfl_xor_sync(0xffffffffu, mx1, 1));
        mx1 = fmaxf(mx1, __shfl_xor_sync(0xffffffffu, mx1, 2));

        float mn0 = fmaxf(m0, mx0), mn1 = fmaxf(m1, mx1);
        float c0 = __expf(m0 - mn0), c1 = __expf(m1 - mn1);
        float rs0 = 0.f, rs1 = 0.f;
#pragma unroll
        for (int nf = 0; nf < 8; nf++) {
            s[nf][0] = __expf(s[nf][0] - mn0);
            s[nf][1] = __expf(s[nf][1] - mn0);
            s[nf][2] = __expf(s[nf][2] - mn1);
            s[nf][3] = __expf(s[nf][3] - mn1);
            rs0 += s[nf][0] + s[nf][1];
            rs1 += s[nf][2] + s[nf][3];
        }
        rs0 += __shfl_xor_sync(0xffffffffu, rs0, 1);
        rs0 += __shfl_xor_sync(0xffffffffu, rs0, 2);
        rs1 += __shfl_xor_sync(0xffffffffu, rs1, 1);
        rs1 += __shfl_xor_sync(0xffffffffu, rs1, 2);
        l0 = l0 * c0 + rs0;
        l1 = l1 * c1 + rs1;
        m0 = mn0; m1 = mn1;
#pragma unroll
        for (int nf = 0; nf < 8; nf++) {
            o[nf][0] *= c0; o[nf][1] *= c0;
            o[nf][2] *= c1; o[nf][3] *= c1;
        }

        // ---- O += P @ V (3xBF16); P A-frags repacked from S C-frags ----
#pragma unroll
        for (int kc = 0; kc < 4; kc++) {
            uint32_t pah[4], pal[4];
            split_pack2(s[2 * kc][0],     s[2 * kc][1],     pah[0], pal[0]);
            split_pack2(s[2 * kc][2],     s[2 * kc][3],     pah[1], pal[1]);
            split_pack2(s[2 * kc + 1][0], s[2 * kc + 1][1], pah[2], pal[2]);
            split_pack2(s[2 * kc + 1][2], s[2 * kc + 1][3], pah[3], pal[3]);
#pragma unroll
            for (int nf = 0; nf < 8; nf++) {
                uint32_t vbh[2], vbl[2];
                uint32_t boff = (uint32_t)(((nf * 8 + b_r) * FP + kc * 16 + b_c) * 2);
                ldsm_x2(vbh, uVh + boff);
                ldsm_x2(vbl, uVl + boff);
                mma_bf16(o[nf], pah, vbh);
                mma_bf16(o[nf], pah, vbl);
                mma_bf16(o[nf], pal, vbh);
            }
        }
    }

    // ---- normalize + store ----
    float i0 = 1.f / l0, i1 = 1.f / l1;
    int row0 = qb * 128 + wid * 16 + g;
#pragma unroll
    for (int nf = 0; nf < 8; nf++) {
        int col = h * DK + nf * 8 + 2 * t;
        *reinterpret_cast<float2*>(O + (size_t)row0 * DM + col) =
            make_float2(o[nf][0] * i0, o[nf][1] * i0);
        *reinterpret_cast<float2*>(O + (size_t)(row0 + 8) * DM + col) =
            make_float2(o[nf][2] * i1, o[nf][3] * i1);
    }
}

// ---------------------------------------------------------------------------
extern "C" void kernel_launch(void* const* d_in, const int* in_sizes, int n_in,
                              void* d_out, int out_size)
{
    const float* query = (const float*)d_in[0];
    const float* key_t = (const float*)d_in[1];
    const float* value = (const float*)d_in[2];
    const float* w_q   = (const float*)d_in[3];
    const float* w_k   = (const float*)d_in[4];
    const float* w_v   = (const float*)d_in[5];
    const float* w_o   = (const float*)d_in[6];
    float* out = (float*)d_out;

    float *Qp, *Kp, *Vp, *Op;
    cudaGetSymbolAddress((void**)&Qp, g_Q);
    cudaGetSymbolAddress((void**)&Kp, g_K);
    cudaGetSymbolAddress((void**)&Vp, g_V);
    cudaGetSymbolAddress((void**)&Op, g_O);
    __nv_bfloat16 *xqh, *xql, *xkh, *xkl, *xvh, *xvl, *oh, *ol;
    __nv_bfloat16 *wqh, *wql, *wkh, *wkl, *wvh, *wvl, *woh, *wol;
    cudaGetSymbolAddress((void**)&xqh, g_xqh); cudaGetSymbolAddress((void**)&xql, g_xql);
    cudaGetSymbolAddress((void**)&xkh, g_xkh); cudaGetSymbolAddress((void**)&xkl, g_xkl);
    cudaGetSymbolAddress((void**)&xvh, g_xvh); cudaGetSymbolAddress((void**)&xvl, g_xvl);
    cudaGetSymbolAddress((void**)&oh,  g_oh);  cudaGetSymbolAddress((void**)&ol,  g_ol);
    cudaGetSymbolAddress((void**)&wqh, g_wqh); cudaGetSymbolAddress((void**)&wql, g_wql);
    cudaGetSymbolAddress((void**)&wkh, g_wkh); cudaGetSymbolAddress((void**)&wkl, g_wkl);
    cudaGetSymbolAddress((void**)&wvh, g_wvh); cudaGetSymbolAddress((void**)&wvl, g_wvl);
    cudaGetSymbolAddress((void**)&woh, g_woh); cudaGetSymbolAddress((void**)&wol, g_wol);

    const int smem_gemm = 4 * 128 * GLD * (int)sizeof(__nv_bfloat16);          // 40960 B
    const int smem_attn = (2 * 128 + 4 * 64) * FP * (int)sizeof(__nv_bfloat16); // 73728 B
    cudaFuncSetAttribute(gemm_mma,  cudaFuncAttributeMaxDynamicSharedMemorySize, smem_gemm);
    cudaFuncSetAttribute(flash_mma, cudaFuncAttributeMaxDynamicSharedMemorySize, smem_attn);

    const int nAct = SEQ * DM, nW = DM * DM;
    split_bf16<<<nAct / 1024, 256>>>(query, xqh, xql, nAct);
    split_bf16<<<nAct / 1024, 256>>>(key_t, xkh, xkl, nAct);
    split_bf16<<<nAct / 1024, 256>>>(value, xvh, xvl, nAct);
    split_bf16<<<nW / 1024, 256>>>(w_q, wqh, wql, nW);
    split_bf16<<<nW / 1024, 256>>>(w_k, wkh, wkl, nW);
    split_bf16<<<nW / 1024, 256>>>(w_v, wvh, wvl, nW);
    split_bf16<<<nW / 1024, 256>>>(w_o, woh, wol, nW);

    dim3 ggrid(DM / 128, SEQ / 128);   // (8, 32)
    gemm_mma<<<ggrid, 256, smem_gemm>>>(xqh, xql, wqh, wql, Qp);
    gemm_mma<<<ggrid, 256, smem_gemm>>>(xkh, xkl, wkh, wkl, Kp);
    gemm_mma<<<ggrid, 256, smem_gemm>>>(xvh, xvl, wvh, wvl, Vp);

    dim3 agrid(NH, SEQ / 128);         // (16, 32)
    flash_mma<<<agrid, 256, smem_attn>>>(Qp, Kp, Vp, Op);

    split_bf16<<<nAct / 1024, 256>>>(Op, oh, ol, nAct);
    gemm_mma<<<ggrid, 256, smem_gemm>>>(oh, ol, woh, wol, out);
}

// round 8
// speedup vs baseline: 2.7076x; 1.3082x over previous
#include <cuda_runtime.h>
#include <cuda_bf16.h>
#include <cstdint>
#include <math.h>

#define SEQ 4096
#define DM  1024
#define NH  16
#define DK  64

using bf16 = __nv_bfloat16;

// ---------------------------------------------------------------------------
// Scratch (__device__ globals: allocation-guard safe) — all bf16 hi/lo pairs
// ---------------------------------------------------------------------------
__device__ bf16 g_xqh[SEQ * DM], g_xql[SEQ * DM];   // input splits
__device__ bf16 g_xkh[SEQ * DM], g_xkl[SEQ * DM];
__device__ bf16 g_xvh[SEQ * DM], g_xvl[SEQ * DM];
__device__ bf16 g_wqh[DM * DM],  g_wql[DM * DM];    // weight splits
__device__ bf16 g_wkh[DM * DM],  g_wkl[DM * DM];
__device__ bf16 g_wvh[DM * DM],  g_wvl[DM * DM];
__device__ bf16 g_woh[DM * DM],  g_wol[DM * DM];
__device__ bf16 g_Qh[SEQ * DM],  g_Ql[SEQ * DM];    // projection outputs
__device__ bf16 g_Kh[SEQ * DM],  g_Kl[SEQ * DM];
__device__ bf16 g_Vh[SEQ * DM],  g_Vl[SEQ * DM];
__device__ bf16 g_oh[SEQ * DM],  g_ol[SEQ * DM];    // attention output

// ---------------------------------------------------------------------------
// PTX helpers — valid at compute_103 (no tcgen05)
// ---------------------------------------------------------------------------
__device__ __forceinline__ uint32_t smem_u32(const void* p) {
    uint32_t a;
    asm("{ .reg .u64 t; cvta.to.shared.u64 t, %1; cvt.u32.u64 %0, t; }" : "=r"(a) : "l"(p));
    return a;
}
__device__ __forceinline__ void ldsm_x4(uint32_t* r, uint32_t addr) {
    asm volatile("ldmatrix.sync.aligned.m8n8.x4.shared.b16 {%0,%1,%2,%3}, [%4];"
                 : "=r"(r[0]), "=r"(r[1]), "=r"(r[2]), "=r"(r[3]) : "r"(addr));
}
__device__ __forceinline__ void ldsm_x2(uint32_t* r, uint32_t addr) {
    asm volatile("ldmatrix.sync.aligned.m8n8.x2.shared.b16 {%0,%1}, [%2];"
                 : "=r"(r[0]), "=r"(r[1]) : "r"(addr));
}
__device__ __forceinline__ void ldsm_x2_trans(uint32_t* r, uint32_t addr) {
    asm volatile("ldmatrix.sync.aligned.m8n8.x2.trans.shared.b16 {%0,%1}, [%2];"
                 : "=r"(r[0]), "=r"(r[1]) : "r"(addr));
}
__device__ __forceinline__ void mma_bf16(float* c, const uint32_t* a, const uint32_t* b) {
    asm volatile(
        "mma.sync.aligned.m16n8k16.row.col.f32.bf16.bf16.f32 "
        "{%0,%1,%2,%3}, {%4,%5,%6,%7}, {%8,%9}, {%0,%1,%2,%3};"
        : "+f"(c[0]), "+f"(c[1]), "+f"(c[2]), "+f"(c[3])
        : "r"(a[0]), "r"(a[1]), "r"(a[2]), "r"(a[3]), "r"(b[0]), "r"(b[1]));
}
__device__ __forceinline__ void cp16(uint32_t s, const void* g) {
    asm volatile("cp.async.cg.shared.global [%0], [%1], 16;" :: "r"(s), "l"(g));
}
#define CP_COMMIT() asm volatile("cp.async.commit_group;" ::: "memory")
#define CP_WAIT(n)  asm volatile("cp.async.wait_group %0;" :: "n"(n) : "memory")

__device__ __forceinline__ void split_pack2(float x, float y, uint32_t& hi, uint32_t& lo) {
    __nv_bfloat162 h2 = __floats2bfloat162_rn(x, y);
    float rx = x - __bfloat162float(h2.x);
    float ry = y - __bfloat162float(h2.y);
    __nv_bfloat162 l2 = __floats2bfloat162_rn(rx, ry);
    hi = *reinterpret_cast<uint32_t*>(&h2);
    lo = *reinterpret_cast<uint32_t*>(&l2);
}

// ---------------------------------------------------------------------------
// fp32 -> bf16 hi/lo split (inputs + weights)
// ---------------------------------------------------------------------------
__global__ __launch_bounds__(256) void split_bf16(
    const float* __restrict__ x, bf16* __restrict__ h, bf16* __restrict__ l, int n)
{
    int i = (blockIdx.x * 256 + threadIdx.x) * 4;
    if (i >= n) return;
    float4 v = *reinterpret_cast<const float4*>(x + i);
    uint32_t h01, l01, h23, l23;
    split_pack2(v.x, v.y, h01, l01);
    split_pack2(v.z, v.w, h23, l23);
    *reinterpret_cast<uint32_t*>(h + i)     = h01;
    *reinterpret_cast<uint32_t*>(h + i + 2) = h23;
    *reinterpret_cast<uint32_t*>(l + i)     = l01;
    *reinterpret_cast<uint32_t*>(l + i + 2) = l23;
}

// ---------------------------------------------------------------------------
// HMMA GEMM: Y = A @ B^T, 3xBF16 split, cp.async double-buffered.
// CTA 128x128 (8 warps 64x32), BK=32, pitch GLD=40 bf16 (80 B, 16B-multiple).
// SPLIT_OUT: write bf16 hi/lo (for Q/K/V proj); else fp32 (final).
// ---------------------------------------------------------------------------
#define GLD 40
#define GSTAGE_B 40960   // 4 tiles * 128 * GLD * 2 bytes

template<bool SPLIT_OUT>
__global__ __launch_bounds__(256) void gemm_mma(
    const bf16* __restrict__ Ah, const bf16* __restrict__ Al,
    const bf16* __restrict__ Bh, const bf16* __restrict__ Bl,
    float* __restrict__ Yf, bf16* __restrict__ Yh, bf16* __restrict__ Yl)
{
    extern __shared__ __align__(16) bf16 smg[];
    const int tid  = threadIdx.x;
    const int lane = tid & 31;
    const int wid  = tid >> 5;
    const int wm   = wid >> 2;
    const int wn   = wid & 3;
    const int bm   = blockIdx.y, bn = blockIdx.x;
    const uint32_t uS = smem_u32(smg);

    auto issue = [&](int ktile) {
        const int kt = ktile * 32;
        const uint32_t sbase = uS + (ktile & 1) * GSTAGE_B;
#pragma unroll
        for (int it = 0; it < 8; it++) {
            int idx  = tid + it * 256;           // 0..2047
            int tile = idx >> 9;                 // 0..3: Ah,Al,Bh,Bl
            int rem  = idx & 511;
            int r    = rem >> 2, j = rem & 3;
            const bf16* gp = (tile == 0 ? Ah : tile == 1 ? Al : tile == 2 ? Bh : Bl);
            int row = ((tile < 2) ? bm : bn) * 128 + r;
            cp16(sbase + tile * 10240 + r * 80 + j * 16,
                 gp + (size_t)row * DM + kt + j * 8);
        }
    };

    float acc[4][4][4];
#pragma unroll
    for (int i = 0; i < 4; i++)
#pragma unroll
        for (int j = 0; j < 4; j++)
#pragma unroll
            for (int k = 0; k < 4; k++) acc[i][j][k] = 0.f;

    const int a_r = (lane & 15), a_c = (lane >> 4) * 8;
    const int b_r = (lane & 7),  b_c = ((lane >> 3) & 1) * 8;

    issue(0);
    CP_COMMIT();

    for (int kt = 0; kt < 32; kt++) {
        if (kt + 1 < 32) { issue(kt + 1); CP_COMMIT(); CP_WAIT(1); }
        else             { CP_WAIT(0); }
        __syncthreads();

        const uint32_t st = uS + (kt & 1) * GSTAGE_B;
        const uint32_t uAh = st, uAl = st + 10240, uBh = st + 20480, uBl = st + 30720;

#pragma unroll
        for (int s = 0; s < 2; s++) {
            uint32_t ah[4][4], al[4][4], bh[4][2], bl[4][2];
#pragma unroll
            for (int i = 0; i < 4; i++) {
                uint32_t off = (uint32_t)(((wm * 64 + i * 16 + a_r) * GLD + s * 16 + a_c) * 2);
                ldsm_x4(ah[i], uAh + off);
                ldsm_x4(al[i], uAl + off);
            }
#pragma unroll
            for (int j = 0; j < 4; j++) {
                uint32_t off = (uint32_t)(((wn * 32 + j * 8 + b_r) * GLD + s * 16 + b_c) * 2);
                ldsm_x2(bh[j], uBh + off);
                ldsm_x2(bl[j], uBl + off);
            }
#pragma unroll
            for (int i = 0; i < 4; i++)
#pragma unroll
                for (int j = 0; j < 4; j++) {
                    mma_bf16(acc[i][j], ah[i], bh[j]);
                    mma_bf16(acc[i][j], ah[i], bl[j]);
                    mma_bf16(acc[i][j], al[i], bh[j]);
                }
        }
        __syncthreads();
    }

    const int g = lane >> 2, t = lane & 3;
#pragma unroll
    for (int i = 0; i < 4; i++) {
        int row0 = bm * 128 + wm * 64 + i * 16 + g;
#pragma unroll
        for (int j = 0; j < 4; j++) {
            int col = bn * 128 + wn * 32 + j * 8 + 2 * t;
            if (SPLIT_OUT) {
                uint32_t hi, lo;
                split_pack2(acc[i][j][0], acc[i][j][1], hi, lo);
                *reinterpret_cast<uint32_t*>(Yh + (size_t)row0 * DM + col) = hi;
                *reinterpret_cast<uint32_t*>(Yl + (size_t)row0 * DM + col) = lo;
                split_pack2(acc[i][j][2], acc[i][j][3], hi, lo);
                *reinterpret_cast<uint32_t*>(Yh + (size_t)(row0 + 8) * DM + col) = hi;
                *reinterpret_cast<uint32_t*>(Yl + (size_t)(row0 + 8) * DM + col) = lo;
            } else {
                *reinterpret_cast<float2*>(Yf + (size_t)row0 * DM + col) =
                    make_float2(acc[i][j][0], acc[i][j][1]);
                *reinterpret_cast<float2*>(Yf + (size_t)(row0 + 8) * DM + col) =
                    make_float2(acc[i][j][2], acc[i][j][3]);
            }
        }
    }
}

// ---------------------------------------------------------------------------
// HMMA flash attention, all operands pre-split bf16, cp.async double-buffered.
// CTA = (head, 128 Q rows); 8 warps x (16 rows x 64 cols); Bc = 64.
// Q/K natural [row][d]; V natural [kv][d] consumed via ldmatrix.trans.
// P stays in registers (S C-frags repack into PV A-frags).
// Scale 1/8 applied to S (exact). Output written as bf16 hi/lo.
// ---------------------------------------------------------------------------
#define FP 72            // pitch bf16 (144 B = 16B-multiple, ldsm conflict-free)
#define Q_BYTES   36864  // 2 * 128 * FP * 2
#define KV_STAGE  36864  // 4 * 64 * FP * 2

__global__ __launch_bounds__(256) void flash_mma(
    const bf16* __restrict__ Qh, const bf16* __restrict__ Ql,
    const bf16* __restrict__ Kh, const bf16* __restrict__ Kl,
    const bf16* __restrict__ Vh, const bf16* __restrict__ Vl,
    bf16* __restrict__ Oh, bf16* __restrict__ Ol)
{
    extern __shared__ __align__(16) bf16 sb[];
    const int tid  = threadIdx.x;
    const int lane = tid & 31;
    const int wid  = tid >> 5;
    const int g    = lane >> 2;
    const int t    = lane & 3;
    const int h    = blockIdx.x;
    const int qb   = blockIdx.y;
    const uint32_t uS = smem_u32(sb);

    auto issue_kv = [&](int kv) {
        const uint32_t base = uS + Q_BYTES + (kv & 1) * KV_STAGE;
#pragma unroll
        for (int it = 0; it < 8; it++) {
            int idx = tid + it * 256;            // 0..2047
            int arr = idx >> 9;                  // Kh,Kl,Vh,Vl
            int rem = idx & 511;
            int r   = rem >> 3, j = rem & 7;
            const bf16* gp = (arr == 0 ? Kh : arr == 1 ? Kl : arr == 2 ? Vh : Vl);
            cp16(base + arr * 9216 + r * 144 + j * 16,
                 gp + (size_t)(kv * 64 + r) * DM + h * DK + j * 8);
        }
    };

    // issue Q (once) + first KV stage
#pragma unroll
    for (int it = 0; it < 8; it++) {
        int idx = tid + it * 256;                // 0..2047
        int arr = idx >> 10;                     // Qh, Ql
        int rem = idx & 1023;
        int r   = rem >> 3, j = rem & 7;
        const bf16* gp = arr ? Ql : Qh;
        cp16(uS + arr * 18432 + r * 144 + j * 16,
             gp + (size_t)(qb * 128 + r) * DM + h * DK + j * 8);
    }
    issue_kv(0);
    CP_COMMIT();

    const int a_r = (lane & 15), a_c = (lane >> 4) * 8;
    const int b_r = (lane & 7),  b_c = ((lane >> 3) & 1) * 8;
    const int v_r = (lane & 15);

    float o[8][4];
#pragma unroll
    for (int nf = 0; nf < 8; nf++)
#pragma unroll
        for (int k = 0; k < 4; k++) o[nf][k] = 0.f;
    float m0 = -1e30f, m1 = -1e30f, l0 = 0.f, l1 = 0.f;

    for (int kv = 0; kv < SEQ / 64; kv++) {
        if (kv + 1 < SEQ / 64) { issue_kv(kv + 1); CP_COMMIT(); CP_WAIT(1); }
        else                   { CP_WAIT(0); }
        __syncthreads();

        const uint32_t kb  = uS + Q_BYTES + (kv & 1) * KV_STAGE;
        const uint32_t uKh = kb, uKl = kb + 9216, uVh = kb + 18432, uVl = kb + 27648;

        // ---- S = Q @ K^T (3xBF16) ----
        float s[8][4];
#pragma unroll
        for (int nf = 0; nf < 8; nf++)
#pragma unroll
            for (int k = 0; k < 4; k++) s[nf][k] = 0.f;

#pragma unroll
        for (int kc = 0; kc < 4; kc++) {
            uint32_t ah[4], al[4];
            uint32_t aoff = (uint32_t)(((wid * 16 + a_r) * FP + kc * 16 + a_c) * 2);
            ldsm_x4(ah, uS + aoff);
            ldsm_x4(al, uS + 18432 + aoff);
#pragma unroll
            for (int nf = 0; nf < 8; nf++) {
                uint32_t bh[2], bl[2];
                uint32_t boff = (uint32_t)(((nf * 8 + b_r) * FP + kc * 16 + b_c) * 2);
                ldsm_x2(bh, uKh + boff);
                ldsm_x2(bl, uKl + boff);
                mma_bf16(s[nf], ah, bh);
                mma_bf16(s[nf], ah, bl);
                mma_bf16(s[nf], al, bh);
            }
        }

        // ---- scale + online softmax (rows g / g+8, quad-reduce over t) ----
        float mx0 = -1e30f, mx1 = -1e30f;
#pragma unroll
        for (int nf = 0; nf < 8; nf++) {
            s[nf][0] *= 0.125f; s[nf][1] *= 0.125f;
            s[nf][2] *= 0.125f; s[nf][3] *= 0.125f;
            mx0 = fmaxf(mx0, fmaxf(s[nf][0], s[nf][1]));
            mx1 = fmaxf(mx1, fmaxf(s[nf][2], s[nf][3]));
        }
        mx0 = fmaxf(mx0, __shfl_xor_sync(0xffffffffu, mx0, 1));
        mx0 = fmaxf(mx0, __shfl_xor_sync(0xffffffffu, mx0, 2));
        mx1 = fmaxf(mx1, __shfl_xor_sync(0xffffffffu, mx1, 1));
        mx1 = fmaxf(mx1, __shfl_xor_sync(0xffffffffu, mx1, 2));

        float mn0 = fmaxf(m0, mx0), mn1 = fmaxf(m1, mx1);
        float c0 = __expf(m0 - mn0), c1 = __expf(m1 - mn1);
        float rs0 = 0.f, rs1 = 0.f;
#pragma unroll
        for (int nf = 0; nf < 8; nf++) {
            s[nf][0] = __expf(s[nf][0] - mn0);
            s[nf][1] = __expf(s[nf][1] - mn0);
            s[nf][2] = __expf(s[nf][2] - mn1);
            s[nf][3] = __expf(s[nf][3] - mn1);
            rs0 += s[nf][0] + s[nf][1];
            rs1 += s[nf][2] + s[nf][3];
        }
        rs0 += __shfl_xor_sync(0xffffffffu, rs0, 1);
        rs0 += __shfl_xor_sync(0xffffffffu, rs0, 2);
        rs1 += __shfl_xor_sync(0xffffffffu, rs1, 1);
        rs1 += __shfl_xor_sync(0xffffffffu, rs1, 2);
        l0 = l0 * c0 + rs0;
        l1 = l1 * c1 + rs1;
        m0 = mn0; m1 = mn1;
#pragma unroll
        for (int nf = 0; nf < 8; nf++) {
            o[nf][0] *= c0; o[nf][1] *= c0;
            o[nf][2] *= c1; o[nf][3] *= c1;
        }

        // ---- O += P @ V (3xBF16); V B-frags via ldmatrix.trans ----
#pragma unroll
        for (int kc = 0; kc < 4; kc++) {
            uint32_t pah[4], pal[4];
            split_pack2(s[2 * kc][0],     s[2 * kc][1],     pah[0], pal[0]);
            split_pack2(s[2 * kc][2],     s[2 * kc][3],     pah[1], pal[1]);
            split_pack2(s[2 * kc + 1][0], s[2 * kc + 1][1], pah[2], pal[2]);
            split_pack2(s[2 * kc + 1][2], s[2 * kc + 1][3], pah[3], pal[3]);
#pragma unroll
            for (int nf = 0; nf < 8; nf++) {
                uint32_t vbh[2], vbl[2];
                uint32_t voff = (uint32_t)(((kc * 16 + v_r) * FP + nf * 8) * 2);
                ldsm_x2_trans(vbh, uVh + voff);
                ldsm_x2_trans(vbl, uVl + voff);
                mma_bf16(o[nf], pah, vbh);
                mma_bf16(o[nf], pah, vbl);
                mma_bf16(o[nf], pal, vbh);
            }
        }
        __syncthreads();
    }

    // ---- normalize + store as bf16 hi/lo ----
    float i0 = 1.f / l0, i1 = 1.f / l1;
    int row0 = qb * 128 + wid * 16 + g;
#pragma unroll
    for (int nf = 0; nf < 8; nf++) {
        int col = h * DK + nf * 8 + 2 * t;
        uint32_t hi, lo;
        split_pack2(o[nf][0] * i0, o[nf][1] * i0, hi, lo);
        *reinterpret_cast<uint32_t*>(Oh + (size_t)row0 * DM + col) = hi;
        *reinterpret_cast<uint32_t*>(Ol + (size_t)row0 * DM + col) = lo;
        split_pack2(o[nf][2] * i1, o[nf][3] * i1, hi, lo);
        *reinterpret_cast<uint32_t*>(Oh + (size_t)(row0 + 8) * DM + col) = hi;
        *reinterpret_cast<uint32_t*>(Ol + (size_t)(row0 + 8) * DM + col) = lo;
    }
}

// ---------------------------------------------------------------------------
extern "C" void kernel_launch(void* const* d_in, const int* in_sizes, int n_in,
                              void* d_out, int out_size)
{
    const float* query = (const float*)d_in[0];
    const float* key_t = (const float*)d_in[1];
    const float* value = (const float*)d_in[2];
    const float* w_q   = (const float*)d_in[3];
    const float* w_k   = (const float*)d_in[4];
    const float* w_v   = (const float*)d_in[5];
    const float* w_o   = (const float*)d_in[6];
    float* out = (float*)d_out;

    bf16 *xqh, *xql, *xkh, *xkl, *xvh, *xvl;
    bf16 *wqh, *wql, *wkh, *wkl, *wvh, *wvl, *woh, *wol;
    bf16 *Qh, *Ql, *Kh, *Kl, *Vh, *Vl, *oh, *ol;
    cudaGetSymbolAddress((void**)&xqh, g_xqh); cudaGetSymbolAddress((void**)&xql, g_xql);
    cudaGetSymbolAddress((void**)&xkh, g_xkh); cudaGetSymbolAddress((void**)&xkl, g_xkl);
    cudaGetSymbolAddress((void**)&xvh, g_xvh); cudaGetSymbolAddress((void**)&xvl, g_xvl);
    cudaGetSymbolAddress((void**)&wqh, g_wqh); cudaGetSymbolAddress((void**)&wql, g_wql);
    cudaGetSymbolAddress((void**)&wkh, g_wkh); cudaGetSymbolAddress((void**)&wkl, g_wkl);
    cudaGetSymbolAddress((void**)&wvh, g_wvh); cudaGetSymbolAddress((void**)&wvl, g_wvl);
    cudaGetSymbolAddress((void**)&woh, g_woh); cudaGetSymbolAddress((void**)&wol, g_wol);
    cudaGetSymbolAddress((void**)&Qh,  g_Qh);  cudaGetSymbolAddress((void**)&Ql,  g_Ql);
    cudaGetSymbolAddress((void**)&Kh,  g_Kh);  cudaGetSymbolAddress((void**)&Kl,  g_Kl);
    cudaGetSymbolAddress((void**)&Vh,  g_Vh);  cudaGetSymbolAddress((void**)&Vl,  g_Vl);
    cudaGetSymbolAddress((void**)&oh,  g_oh);  cudaGetSymbolAddress((void**)&ol,  g_ol);

    const int smem_gemm = 2 * GSTAGE_B;              // 81920 B
    const int smem_attn = Q_BYTES + 2 * KV_STAGE;    // 110592 B
    cudaFuncSetAttribute(gemm_mma<true>,  cudaFuncAttributeMaxDynamicSharedMemorySize, smem_gemm);
    cudaFuncSetAttribute(gemm_mma<false>, cudaFuncAttributeMaxDynamicSharedMemorySize, smem_gemm);
    cudaFuncSetAttribute(flash_mma,       cudaFuncAttributeMaxDynamicSharedMemorySize, smem_attn);

    const int nAct = SEQ * DM, nW = DM * DM;
    split_bf16<<<nAct / 1024, 256>>>(query, xqh, xql, nAct);
    split_bf16<<<nAct / 1024, 256>>>(key_t, xkh, xkl, nAct);
    split_bf16<<<nAct / 1024, 256>>>(value, xvh, xvl, nAct);
    split_bf16<<<nW / 1024, 256>>>(w_q, wqh, wql, nW);
    split_bf16<<<nW / 1024, 256>>>(w_k, wkh, wkl, nW);
    split_bf16<<<nW / 1024, 256>>>(w_v, wvh, wvl, nW);
    split_bf16<<<nW / 1024, 256>>>(w_o, woh, wol, nW);

    dim3 ggrid(DM / 128, SEQ / 128);   // (8, 32)
    gemm_mma<true><<<ggrid, 256, smem_gemm>>>(xqh, xql, wqh, wql, nullptr, Qh, Ql);
    gemm_mma<true><<<ggrid, 256, smem_gemm>>>(xkh, xkl, wkh, wkl, nullptr, Kh, Kl);
    gemm_mma<true><<<ggrid, 256, smem_gemm>>>(xvh, xvl, wvh, wvl, nullptr, Vh, Vl);

    dim3 agrid(NH, SEQ / 128);         // (16, 32)
    flash_mma<<<agrid, 256, smem_attn>>>(Qh, Ql, Kh, Kl, Vh, Vl, oh, ol);

    gemm_mma<false><<<ggrid, 256, smem_gemm>>>(oh, ol, woh, wol, out, nullptr, nullptr);
}